// round 7
// baseline (speedup 1.0000x reference)
#include <cuda_runtime.h>

// Problem shape (fixed by setup_inputs): B=256, N=65536, half=32768.
#define NCOL    65536
#define HALF    32768
#define C4ROW   8192            // float4 per half-row
#define C4F4    16384           // float4 per full row
#define BPR     128             // warp-blocks per row (64 c4 each)
#define BDIM    512
#define NCTA    296
#define NROWMAX 512

#define THRESH  0.01f
#define PENALTY 2.0f

// Zero-initialized; every slot is reset by its last reader -> clean graph replays.
__device__ float    g_cta[NCTA];
__device__ float    g_rowcorr[NROWMAX];
__device__ int      g_encf_r[NROWMAX];   // atomicMax of (C4ROW - min_c4); 0 = none
__device__ int      g_encl_r[NROWMAX];   // atomicMax of (max_c4 + 1);     0 = none
__device__ int      g_encf_i[NROWMAX];
__device__ int      g_encl_i[NROWMAX];
__device__ unsigned g_rowcnt[NROWMAX];
__device__ unsigned g_done = 0;

__device__ __forceinline__ float max4abs(float4 v) {
    return fmaxf(fmaxf(fabsf(v.x), fabsf(v.y)), fmaxf(fabsf(v.z), fabsf(v.w)));
}

__device__ __forceinline__ float loss4(float4 L, float4 Li, float4 P, float4 Pi, float acc) {
    #pragma unroll
    for (int k = 0; k < 4; k++) {
        float lr = (&L.x)[k],  li = (&Li.x)[k];
        float pr = (&P.x)[k],  pi = (&Pi.x)[k];
        float dr = pr - lr;
        float di = pi - li;
        float dint = fmaf(pi, pi, pr * pr) - fmaf(li, li, lr * lr);
        acc = fmaf(dr, dr, acc);
        acc = fmaf(di, di, acc);
        acc = fmaf(50.0f * dint, dint, acc);
    }
    return acc;
}

// Row correction: (PENALTY-1) * sum of squared diff outside [first,last].
// Executed by the warp that draws the row's final arrival ticket. The VALUE is
// row-deterministic (independent of which warp runs it), so the fixed-order
// final fold keeps the output bitwise deterministic.
__device__ __forceinline__ void do_correction(int prow,
                                              const float* __restrict__ lab,
                                              const float* __restrict__ pred,
                                              int lane)
{
    __threadfence();   // acquire: all 128 blocks' atomicMax results visible
    int efr = g_encf_r[prow], elr = g_encl_r[prow];
    int efi = g_encf_i[prow], eli = g_encl_i[prow];
    const float* Lr = lab  + (size_t)prow * NCOL;
    const float* Pr = pred + (size_t)prow * NCOL;
    const float* Lj = Lr + HALF;
    const float* Pj = Pr + HALF;

    int fr = 0, lrr = HALF - 1, fi = 0, lii = HALF - 1;
    if (elr > 0) {   // refine 4-granular bounds to element-exact (<=3 steps each)
        fr  = (C4ROW - efr) * 4; while (fabsf(Lr[fr])  <= THRESH) fr++;
        lrr = (elr - 1) * 4 + 3; while (fabsf(Lr[lrr]) <= THRESH) lrr--;
    }
    if (eli > 0) {
        fi  = (C4ROW - efi) * 4; while (fabsf(Lj[fi])  <= THRESH) fi++;
        lii = (eli - 1) * 4 + 3; while (fabsf(Lj[lii]) <= THRESH) lii--;
    }

    float corr = 0.0f;   // outside region is typically a handful of elements
    for (int j = lane;           j < fr;   j += 32) { float d = Pr[j] - Lr[j]; corr = fmaf(d, d, corr); }
    for (int j = lrr + 1 + lane; j < HALF; j += 32) { float d = Pr[j] - Lr[j]; corr = fmaf(d, d, corr); }
    for (int j = lane;           j < fi;   j += 32) { float d = Pj[j] - Lj[j]; corr = fmaf(d, d, corr); }
    for (int j = lii + 1 + lane; j < HALF; j += 32) { float d = Pj[j] - Lj[j]; corr = fmaf(d, d, corr); }
    #pragma unroll
    for (int off = 16; off > 0; off >>= 1)
        corr += __shfl_xor_sync(0xFFFFFFFFu, corr, off);

    if (lane == 0) {
        g_rowcorr[prow] = (PENALTY - 1.0f) * corr;
        g_encf_r[prow] = 0; g_encl_r[prow] = 0;   // reset for next graph replay
        g_encf_i[prow] = 0; g_encl_i[prow] = 0;
        g_rowcnt[prow] = 0;
        __threadfence();
    }
}

__global__ __launch_bounds__(BDIM, 2)
void loss_kernel(const float* __restrict__ pred,
                 const float* __restrict__ lab,
                 float* __restrict__ out,
                 int B)
{
    const int tid  = threadIdx.x;
    const int lane = tid & 31;
    const int warp = tid >> 5;
    const int gw   = blockIdx.x * (BDIM / 32) + warp;   // global warp id
    const int nw   = NCTA * (BDIM / 32);                // 4736 warps
    const int nblks = B * BPR;                          // 32768

    float acc = 0.0f;
    int pend_row = -1;
    unsigned pend_tk = 0;   // valid in lane 0

    // ======== warp-autonomous streaming loop: no block syncs anywhere ========
    for (int blk = gw; blk < nblks; blk += nw) {
        const int row = blk >> 7;                 // BPR = 128
        const int cb  = (blk & (BPR - 1)) << 6;   // block base c4 within half
        const float4* R = (const float4*)lab  + (size_t)row * C4F4;
        const float4* P = (const float4*)pred + (size_t)row * C4F4;
        const int ca = cb + lane;
        const int cc = ca + 32;

        // issue all 8 loads first
        float4 L0  = R[ca];          float4 L1  = R[cc];
        float4 Li0 = R[C4ROW + ca];  float4 Li1 = R[C4ROW + cc];
        float4 P0  = P[ca];          float4 P1  = P[cc];
        float4 Pi0 = P[C4ROW + ca];  float4 Pi1 = P[C4ROW + cc];

        // consume PREVIOUS block's arrival ticket now (atomic latency hidden
        // behind this block's loads)
        if (pend_row >= 0) {
            unsigned pt = __shfl_sync(0xFFFFFFFFu, pend_tk, 0);
            if (pt == BPR - 1)
                do_correction(pend_row, lab, pred, lane);
        }

        acc = loss4(L0, Li0, P0, Pi0, acc);
        acc = loss4(L1, Li1, P1, Pi1, acc);

        // significant-index tracking purely via ballots (lanes are c4-ordered)
        unsigned b0r = __ballot_sync(0xFFFFFFFFu, max4abs(L0)  > THRESH);
        unsigned b1r = __ballot_sync(0xFFFFFFFFu, max4abs(L1)  > THRESH);
        unsigned b0i = __ballot_sync(0xFFFFFFFFu, max4abs(Li0) > THRESH);
        unsigned b1i = __ballot_sync(0xFFFFFFFFu, max4abs(Li1) > THRESH);

        if (lane == 0) {
            if (b0r | b1r) {
                int mn = b0r ? cb + (__ffs(b0r) - 1)        : cb + 32 + (__ffs(b1r) - 1);
                int mx = b1r ? cb + 32 + (31 - __clz(b1r))  : cb + (31 - __clz(b0r));
                atomicMax(&g_encf_r[row], C4ROW - mn);   // no return -> RED, no stall
                atomicMax(&g_encl_r[row], mx + 1);
            }
            if (b0i | b1i) {
                int mn = b0i ? cb + (__ffs(b0i) - 1)        : cb + 32 + (__ffs(b1i) - 1);
                int mx = b1i ? cb + 32 + (31 - __clz(b1i))  : cb + (31 - __clz(b0i));
                atomicMax(&g_encf_i[row], C4ROW - mn);
                atomicMax(&g_encl_i[row], mx + 1);
            }
            __threadfence();                             // publish before arrival
            pend_tk = atomicAdd(&g_rowcnt[row], 1u);     // consumed next iter
        }
        pend_row = row;
    }
    // flush last pending ticket
    if (pend_row >= 0) {
        unsigned pt = __shfl_sync(0xFFFFFFFFu, pend_tk, 0);
        if (pt == BPR - 1)
            do_correction(pend_row, lab, pred, lane);
    }

    // ======== one epilogue per CTA ========
    __shared__ float s_red[BDIM / 32];
    __shared__ float s_fin[BDIM];
    __shared__ bool  s_last;

    #pragma unroll
    for (int off = 16; off > 0; off >>= 1)
        acc += __shfl_xor_sync(0xFFFFFFFFu, acc, off);
    if (lane == 0) s_red[warp] = acc;
    __syncthreads();

    if (tid == 0) {
        float a = 0.0f;
        #pragma unroll
        for (int w = 0; w < BDIM / 32; w++) a += s_red[w];
        g_cta[blockIdx.x] = a;
        __threadfence();
        unsigned t = atomicAdd(&g_done, 1u);
        s_last = (t == (unsigned)(NCTA - 1));
    }
    __syncthreads();
    if (!s_last) return;

    // ======== last CTA: fixed-order fold of CTA partials + row corrections ===
    __threadfence();
    float v = 0.0f;
    for (int i = tid; i < NCTA; i += BDIM) v += g_cta[i];
    for (int i = tid; i < B;    i += BDIM) v += g_rowcorr[i];
    s_fin[tid] = v;
    __syncthreads();
    #pragma unroll
    for (int st = BDIM / 2; st > 0; st >>= 1) {
        if (tid < st) s_fin[tid] += s_fin[tid + st];
        __syncthreads();
    }
    if (tid == 0) {
        out[0] = s_fin[0] / ((float)HALF * (float)B);
        g_done = 0;   // reset for graph replay
    }
}

extern "C" void kernel_launch(void* const* d_in, const int* in_sizes, int n_in,
                              void* d_out, int out_size)
{
    const float* pred = (const float*)d_in[0];
    const float* lab  = (const float*)d_in[1];
    float* out = (float*)d_out;

    const int B = in_sizes[0] / NCOL;   // 256

    loss_kernel<<<NCTA, BDIM>>>(pred, lab, out, B);
}

// round 8
// speedup vs baseline: 1.6764x; 1.6764x over previous
#include <cuda_runtime.h>
#include <limits.h>

// Problem shape (fixed by setup_inputs): B=256, N=65536, half=32768.
#define NCOL   65536
#define HALF   32768
#define C4ROW  8192              // float4 per half-row
#define BDIM   512
#define NITER  (C4ROW / BDIM)    // 16
#define MAXB   1024

#define THRESH  0.01f
#define PENALTY 2.0f

__device__ float        g_partials[MAXB];
__device__ unsigned int g_counter = 0;

__global__ __launch_bounds__(BDIM, 2)
void fused_loss_kernel(const float* __restrict__ pred,
                       const float* __restrict__ lab,
                       float* __restrict__ out,
                       int B)
{
    const int b = blockIdx.x;
    const size_t row = (size_t)b * NCOL;
    const float4* __restrict__ lr4 = (const float4*)(lab  + row);
    const float4* __restrict__ li4 = (const float4*)(lab  + row + HALF);
    const float4* __restrict__ pr4 = (const float4*)(pred + row);
    const float4* __restrict__ pi4 = (const float4*)(pred + row + HALF);

    __shared__ int  s_min_r, s_max_r, s_min_i, s_max_i;
    __shared__ int  s_fr, s_lr, s_fi, s_li;
    __shared__ bool s_is_last;
    if (threadIdx.x == 0) {
        s_min_r = INT_MAX; s_max_r = -1;
        s_min_i = INT_MAX; s_max_i = -1;
    }
    __syncthreads();

    const int lane = threadIdx.x & 31;
    const int warp = threadIdx.x >> 5;

    // ================= SINGLE PASS, ZERO IN-LOOP COLLECTIVES =================
    // Per iter: 4 x LDG.128, FMA chain, per-thread scalar min/max (regs only).
    float acc = 0.0f;
    int minr = INT_MAX, maxr = -1;
    int mini = INT_MAX, maxi = -1;

    #pragma unroll 4
    for (int it = 0; it < NITER; it++) {
        const int c4 = threadIdx.x + it * BDIM;
        float4 L  = lr4[c4];
        float4 Li = li4[c4];
        float4 P  = pr4[c4];
        float4 Pi = pi4[c4];

        float m_r = fmaxf(fmaxf(fabsf(L.x),  fabsf(L.y)),  fmaxf(fabsf(L.z),  fabsf(L.w)));
        float m_i = fmaxf(fmaxf(fabsf(Li.x), fabsf(Li.y)), fmaxf(fabsf(Li.z), fabsf(Li.w)));
        if (m_r > THRESH) { minr = min(minr, c4); maxr = max(maxr, c4); }
        if (m_i > THRESH) { mini = min(mini, c4); maxi = max(maxi, c4); }

        #pragma unroll
        for (int k = 0; k < 4; k++) {
            float lrx = (&L.x)[k],  lix = (&Li.x)[k];
            float prx = (&P.x)[k],  pix = (&Pi.x)[k];
            float dr   = prx - lrx;
            float di   = pix - lix;
            float dint = fmaf(pix, pix, prx * prx) - fmaf(lix, lix, lrx * lrx);
            acc = fmaf(dr, dr, acc);
            acc = fmaf(di, di, acc);
            acc = fmaf(50.0f * dint, dint, acc);
        }
    }

    // ---- one-time min/max reduction (warp shuffle + smem atomics) -----------
    #pragma unroll
    for (int off = 16; off > 0; off >>= 1) {
        minr = min(minr, __shfl_xor_sync(0xFFFFFFFFu, minr, off));
        maxr = max(maxr, __shfl_xor_sync(0xFFFFFFFFu, maxr, off));
        mini = min(mini, __shfl_xor_sync(0xFFFFFFFFu, mini, off));
        maxi = max(maxi, __shfl_xor_sync(0xFFFFFFFFu, maxi, off));
    }
    if (lane == 0) {
        atomicMin(&s_min_r, minr);
        atomicMax(&s_max_r, maxr);
        atomicMin(&s_min_i, mini);
        atomicMax(&s_max_i, maxi);
    }
    __syncthreads();

    // ---- refine 4-granular bounds to element-exact (thread 0, cache hits) ---
    if (threadIdx.x == 0) {
        const float* Lr = lab + row;
        const float* Lj = lab + row + HALF;
        int fr = 0, lrr = HALF - 1, fi = 0, lii = HALF - 1;
        if (s_max_r >= 0) {
            int f = s_min_r * 4;     while (fabsf(Lr[f]) <= THRESH) f++;
            int l = s_max_r * 4 + 3; while (fabsf(Lr[l]) <= THRESH) l--;
            fr = f; lrr = l;
        }
        if (s_max_i >= 0) {
            int f = s_min_i * 4;     while (fabsf(Lj[f]) <= THRESH) f++;
            int l = s_max_i * 4 + 3; while (fabsf(Lj[l]) <= THRESH) l--;
            fi = f; lii = l;
        }
        s_fr = fr; s_lr = lrr; s_fi = fi; s_li = lii;
    }
    __syncthreads();

    // ---- correction: (P-1) * sum of d^2 outside [first,last] (tiny region) --
    {
        const float* Lr = lab  + row;
        const float* Pr = pred + row;
        const float* Lj = lab  + row + HALF;
        const float* Pj = pred + row + HALF;
        const int fr = s_fr, lrr = s_lr, fi = s_fi, lii = s_li;
        float corr = 0.0f;
        for (int j = threadIdx.x; j < fr; j += BDIM)            { float d = Pr[j] - Lr[j]; corr = fmaf(d, d, corr); }
        for (int j = lrr + 1 + threadIdx.x; j < HALF; j += BDIM){ float d = Pr[j] - Lr[j]; corr = fmaf(d, d, corr); }
        for (int j = threadIdx.x; j < fi; j += BDIM)            { float d = Pj[j] - Lj[j]; corr = fmaf(d, d, corr); }
        for (int j = lii + 1 + threadIdx.x; j < HALF; j += BDIM){ float d = Pj[j] - Lj[j]; corr = fmaf(d, d, corr); }
        acc = fmaf(PENALTY - 1.0f, corr, acc);
    }

    // ---- block sum reduction -------------------------------------------------
    __shared__ float s_warp[BDIM / 32];
    #pragma unroll
    for (int off = 16; off > 0; off >>= 1)
        acc += __shfl_xor_sync(0xFFFFFFFFu, acc, off);
    if (lane == 0)
        s_warp[warp] = acc;
    __syncthreads();
    if (threadIdx.x < 32) {
        float v = (threadIdx.x < BDIM / 32) ? s_warp[threadIdx.x] : 0.0f;
        #pragma unroll
        for (int off = 16; off > 0; off >>= 1)
            v += __shfl_xor_sync(0xFFFFFFFFu, v, off);
        if (threadIdx.x == 0)
            g_partials[b] = v;
    }

    // ---- last CTA folds the per-row partials (self-resetting for graphs) ----
    if (threadIdx.x == 0) {
        __threadfence();
        unsigned int ticket = atomicAdd(&g_counter, 1u);
        s_is_last = (ticket == (unsigned int)(B - 1));
    }
    __syncthreads();

    if (s_is_last) {
        __threadfence();
        __shared__ float s_fin[256];
        if (threadIdx.x < 256)
            s_fin[threadIdx.x] = (threadIdx.x < B) ? g_partials[threadIdx.x] : 0.0f;
        __syncthreads();
        #pragma unroll
        for (int st = 128; st > 0; st >>= 1) {
            if (threadIdx.x < st) s_fin[threadIdx.x] += s_fin[threadIdx.x + st];
            __syncthreads();
        }
        if (threadIdx.x == 0) {
            out[0] = s_fin[0] / ((float)HALF * (float)B);
            g_counter = 0;   // reset for graph replay
        }
    }
}

extern "C" void kernel_launch(void* const* d_in, const int* in_sizes, int n_in,
                              void* d_out, int out_size)
{
    const float* pred = (const float*)d_in[0];
    const float* lab  = (const float*)d_in[1];
    float* out = (float*)d_out;

    const int B = in_sizes[0] / NCOL;   // 256

    fused_loss_kernel<<<B, BDIM>>>(pred, lab, out, B);
}